// round 13
// baseline (speedup 1.0000x reference)
#include <cuda_runtime.h>
#include <cstdint>

#define NN        8192
#define KSEL      64
#define NTHREADS  256
#define WCAP      32             // per-warp candidate slots (5.6 sigma; overflow -> exact fallback)
#define FCAP      (8 * WCAP)     // 256
#define THRESH    2.25f

#define ROWB      (NN * 4)       // 32768-byte row buffer
#define OFF_BUF   0
#define OFF_SEG   32768          // 2048 (256 x u64); fallback: hist (1KB) then fcand
#define OFF_CNT   34816          // 32: cnt_s[8]
#define OFF_WSUM  34848          // 32
#define OFF_CTR   34880          // 16: fb_count, sh_b, sh_kp, sh_deg
#define OFF_MBAR  34896          // 8
#define SMEM_TOTAL 34904

__device__ __forceinline__ uint64_t make_key(uint32_t bits, uint32_t idx) {
    return ((uint64_t)bits << 16) | (uint64_t)(0xFFFFu ^ idx);
}
__device__ __forceinline__ uint32_t smem_u32(const void* p) {
    return (uint32_t)__cvta_generic_to_shared(p);
}
__device__ __forceinline__ void mbar_init(uint32_t mbar, uint32_t cnt) {
    asm volatile("mbarrier.init.shared.b64 [%0], %1;" :: "r"(mbar), "r"(cnt) : "memory");
}
__device__ __forceinline__ void mbar_expect_tx(uint32_t mbar, uint32_t bytes) {
    asm volatile("mbarrier.arrive.expect_tx.shared.b64 _, [%0], %1;" :: "r"(mbar), "r"(bytes) : "memory");
}
__device__ __forceinline__ void mbar_wait(uint32_t mbar, uint32_t phase) {
    asm volatile(
        "{\n\t.reg .pred P;\n\t"
        "W%=:\n\t"
        "mbarrier.try_wait.parity.acquire.cta.shared::cta.b64 P, [%0], %1, 0x989680;\n\t"
        "@P bra D%=;\n\t"
        "bra W%=;\n\t"
        "D%=:\n\t}"
        :: "r"(mbar), "r"(phase) : "memory");
}
__device__ __forceinline__ void bulk_g2s(uint32_t dst, const void* src, uint32_t bytes, uint32_t mbar) {
    asm volatile("cp.async.bulk.shared::cluster.global.mbarrier::complete_tx::bytes [%0], [%1], %2, [%3];"
                 :: "r"(dst), "l"(src), "r"(bytes), "r"(mbar) : "memory");
}

// Warp-aggregated histogram add (fallback only).
__device__ __forceinline__ void hist_add(uint32_t* hist, uint32_t bin, bool pred, int lane) {
    unsigned act = __ballot_sync(0xffffffffu, pred);
    if (pred) {
        unsigned same   = __match_any_sync(act, bin);
        int      leader = __ffs(same) - 1;
        if (lane == leader) atomicAdd(&hist[bin], (uint32_t)__popc(same));
    }
}

// ============================ Kernel 1: pure write stream ============================
__global__ __launch_bounds__(NTHREADS)
void zero_kernel(float4* __restrict__ out)
{
    const size_t base = (size_t)blockIdx.x * 2048 + threadIdx.x;   // float4 units
    const float4 z4 = make_float4(0.0f, 0.0f, 0.0f, 0.0f);
    #pragma unroll
    for (int u = 0; u < 8; ++u) out[base + (size_t)u * NTHREADS] = z4;
}

// ===================== Kernel 2: pure read stream + tiny scatter =====================
extern __shared__ char smem[];

__global__ __launch_bounds__(NTHREADS)
void topk_mask_kernel(const float* __restrict__ A, float* __restrict__ out)
{
    const int tid  = threadIdx.x;
    const int lane = tid & 31;
    const int warp = tid >> 5;
    const unsigned ltm = (1u << lane) - 1u;
    const size_t row = blockIdx.x;

    uint64_t* seg   = reinterpret_cast<uint64_t*>(smem + OFF_SEG);
    uint32_t* cnt_s = reinterpret_cast<uint32_t*>(smem + OFF_CNT);
    uint32_t* wsum  = reinterpret_cast<uint32_t*>(smem + OFF_WSUM);
    uint32_t* ctr   = reinterpret_cast<uint32_t*>(smem + OFF_CTR);  // fb,b,kp,deg
    const uint32_t mb  = smem_u32(smem + OFF_MBAR);
    const uint32_t bfa = smem_u32(smem + OFF_BUF);

    if (tid == 0) mbar_init(mb, 1);
    __syncthreads();

    const float* arowf = A + row * (size_t)NN;
    float*       orowf = out + row * (size_t)NN;

    // Async read of the whole A-row into smem; warps sleep on the mbarrier.
    if (tid == 0) {
        asm volatile("fence.proxy.async.shared::cta;" ::: "memory");
        mbar_expect_tx(mb, ROWB);
        bulk_g2s(bfa,         arowf,        16384, mb);
        bulk_g2s(bfa + 16384, arowf + 4096, 16384, mb);
    }
    mbar_wait(mb, 0);

    // ---- Sweep from shared memory: ballot-compacted candidate push ----
    const float4* bp = reinterpret_cast<const float4*>(smem + OFF_BUF);
    uint64_t* myseg = seg + (warp << 5);
    uint32_t base = 0;
    #pragma unroll
    for (int u = 0; u < 8; ++u) {
        const float4 v = bp[tid + u * NTHREADS];
        const uint32_t eb = (uint32_t)(tid + u * NTHREADS) * 4u;
        unsigned a;
        a = __ballot_sync(0xffffffffu, v.x >= THRESH);
        if (v.x >= THRESH) { uint32_t o = base + __popc(a & ltm); if (o < WCAP) myseg[o] = make_key(__float_as_uint(v.x), eb + 0u); }
        base += (uint32_t)__popc(a);
        a = __ballot_sync(0xffffffffu, v.y >= THRESH);
        if (v.y >= THRESH) { uint32_t o = base + __popc(a & ltm); if (o < WCAP) myseg[o] = make_key(__float_as_uint(v.y), eb + 1u); }
        base += (uint32_t)__popc(a);
        a = __ballot_sync(0xffffffffu, v.z >= THRESH);
        if (v.z >= THRESH) { uint32_t o = base + __popc(a & ltm); if (o < WCAP) myseg[o] = make_key(__float_as_uint(v.z), eb + 2u); }
        base += (uint32_t)__popc(a);
        a = __ballot_sync(0xffffffffu, v.w >= THRESH);
        if (v.w >= THRESH) { uint32_t o = base + __popc(a & ltm); if (o < WCAP) myseg[o] = make_key(__float_as_uint(v.w), eb + 3u); }
        base += (uint32_t)__popc(a);
    }
    if (lane == 0) cnt_s[warp] = base;
    __syncthreads();

    uint32_t C = 0; bool ok = true;
    #pragma unroll
    for (int w = 0; w < 8; ++w) { const uint32_t cw = cnt_s[w]; C += cw; ok &= (cw <= WCAP); }
    ok = ok && (C >= KSEL);

    if (ok) {
        // ---- Exact rank (value desc, index asc) over per-warp segments ----
        for (int s = tid; s < FCAP; s += NTHREADS) {
            const int w = s >> 5, o = s & (WCAP - 1);
            if ((uint32_t)o < cnt_s[w]) {
                const uint64_t kj = seg[s];
                uint32_t rr = 0;
                #pragma unroll
                for (int w2 = 0; w2 < 8; ++w2) {
                    const uint32_t  n2  = cnt_s[w2];
                    const uint64_t* s2p = seg + (w2 << 5);
                    for (uint32_t m2 = 0; m2 < n2; ++m2)
                        rr += (s2p[m2] > kj) ? 1u : 0u;    // broadcast LDS
                }
                if (rr < KSEL) {
                    const uint32_t idx = 0xFFFFu ^ (uint32_t)(kj & 0xFFFFu);
                    orowf[idx] = __uint_as_float((uint32_t)(kj >> 16));
                }
            }
        }
        return;
    }

    // ============== Exact fallback (rare), data from smem row buffer ==============
    uint32_t* hist = reinterpret_cast<uint32_t*>(smem + OFF_SEG);   // seg dead here
    if (tid < 4) ctr[tid] = 0;              // fb_count, sh_b, sh_kp, sh_deg
    hist[tid] = 0;
    __syncthreads();

    const float* bf = reinterpret_cast<const float*>(smem + OFF_BUF);
    for (int i = tid; i < NN; i += NTHREADS) {
        const float q = bf[i];
        const uint32_t bits = (q > 0.0f) ? __float_as_uint(q) : 0u;
        hist_add(hist, bits >> 24, bits != 0u, lane);
    }
    __syncthreads();

    {   // suffix scan over 256 byte bins
        const uint32_t v0 = hist[tid];
        uint32_t vv = v0;
        #pragma unroll
        for (int d = 1; d < 32; d <<= 1) {
            uint32_t o = __shfl_down_sync(0xffffffffu, vv, d);
            if (lane + d < 32) vv += o;
        }
        if (lane == 0) wsum[warp] = vv;
        __syncthreads();
        uint32_t hi = 0;
        #pragma unroll
        for (int w = 0; w < 8; ++w) if (w > warp) hi += wsum[w];
        const uint32_t s   = vv + hi;
        const uint32_t nxt = s - v0;
        if (tid == 0 && s < KSEL) ctr[3] = 1;
        if (s >= KSEL && nxt < KSEL) { ctr[1] = (uint32_t)tid; ctr[2] = KSEL - nxt; }
        __syncthreads();    // hist dead past this point
    }
    const uint32_t b   = ctr[1];
    const uint32_t kp  = ctr[2];
    const bool     deg = (ctr[3] != 0);
    uint64_t* fcand = seg;                  // overlays dead hist

    for (int i = tid; i < NN; i += NTHREADS) {
        const float q = bf[i];
        const uint32_t bits = (q > 0.0f) ? __float_as_uint(q) : 0u;
        if (deg) {
            if (bits) orowf[i] = q;                    // <K positives: keep all
        } else if (bits) {
            const uint32_t byte = bits >> 24;
            if (byte > b) orowf[i] = q;
            else if (byte == b) {
                const uint32_t pp = atomicAdd(&ctr[0], 1u);
                if (pp < FCAP) fcand[pp] = make_key(bits, (uint32_t)i);
            }
        }
    }
    __syncthreads();

    if (!deg) {
        const uint32_t C2 = ctr[0];
        if (C2 <= FCAP) {
            for (uint32_t j = tid; j < C2; j += NTHREADS) {
                const uint64_t kj = fcand[j];
                uint32_t rr = 0;
                for (uint32_t mm = 0; mm < C2; ++mm)
                    rr += (fcand[mm] > kj) ? 1u : 0u;
                if (rr < kp) {
                    const uint32_t idx = 0xFFFFu ^ (uint32_t)(kj & 0xFFFFu);
                    orowf[idx] = __uint_as_float((uint32_t)(kj >> 16));
                }
            }
        } else {
            // duplicate-heavy pathological rows: O(N) exact rank from smem
            for (int i = tid; i < NN; i += NTHREADS) {
                const float q = bf[i];
                const uint32_t bits = (q > 0.0f) ? __float_as_uint(q) : 0u;
                if (bits && (bits >> 24) == b) {
                    const uint64_t kj = make_key(bits, (uint32_t)i);
                    uint32_t rr = 0;
                    for (int j2 = 0; j2 < NN; ++j2) {
                        const float w2 = bf[j2];
                        const uint32_t wb = (w2 > 0.0f) ? __float_as_uint(w2) : 0u;
                        if (wb && (wb >> 24) == b && make_key(wb, (uint32_t)j2) > kj) ++rr;
                    }
                    if (rr < kp) orowf[i] = q;
                }
            }
        }
    }
}

extern "C" void kernel_launch(void* const* d_in, const int* in_sizes, int n_in,
                              void* d_out, int out_size) {
    const float* A   = (const float*)d_in[0];
    float*       out = (float*)d_out;
    (void)in_sizes; (void)n_in; (void)out_size;   // idx (d_in[1]) unused by the reference
    // Phase 1: pure write stream (zero the output). Phase 2: pure read stream
    // + ~2MB scatter. Stream order guarantees zeros land before the scatter.
    zero_kernel<<<NN, NTHREADS>>>((float4*)out);
    cudaFuncSetAttribute(topk_mask_kernel, cudaFuncAttributeMaxDynamicSharedMemorySize, SMEM_TOTAL);
    topk_mask_kernel<<<NN, NTHREADS, SMEM_TOTAL>>>(A, out);
}

// round 14
// speedup vs baseline: 1.3413x; 1.3413x over previous
#include <cuda_runtime.h>
#include <cstdint>

#define NN        8192
#define KSEL      64
#define NTHREADS  256
#define FCAP      320            // dense candidate cap (~16 sigma above E[C]=100)
#define THRESH    2.25f
#define TBI       0x40100000     // float bits of 2.25f (int compare valid: thresh > 0)

#define ROWB      (NN * 4)       // 32768-byte row buffer
#define OFF_BUF   0
#define OFF_ZBUF  32768          // 2048 zero tile
#define OFF_CAND  34816          // 2560 (320 x u64); fallback: hist(1KB) then fcand
#define OFF_WSUM  37376          // 32
#define OFF_CTR   37408          // 16: cand/fb count, sh_b, sh_kp, sh_deg
#define OFF_MBAR  37424          // 8
#define SMEM_TOTAL 37432

__device__ __forceinline__ uint64_t make_key(uint32_t bits, uint32_t idx) {
    // larger key == larger value; ties -> smaller index (top_k order)
    return ((uint64_t)bits << 16) | (uint64_t)(0xFFFFu ^ idx);
}
__device__ __forceinline__ uint32_t smem_u32(const void* p) {
    return (uint32_t)__cvta_generic_to_shared(p);
}
__device__ __forceinline__ void mbar_init(uint32_t mbar, uint32_t cnt) {
    asm volatile("mbarrier.init.shared.b64 [%0], %1;" :: "r"(mbar), "r"(cnt) : "memory");
}
__device__ __forceinline__ void mbar_expect_tx(uint32_t mbar, uint32_t bytes) {
    asm volatile("mbarrier.arrive.expect_tx.shared.b64 _, [%0], %1;" :: "r"(mbar), "r"(bytes) : "memory");
}
__device__ __forceinline__ void mbar_wait(uint32_t mbar, uint32_t phase) {
    asm volatile(
        "{\n\t.reg .pred P;\n\t"
        "W%=:\n\t"
        "mbarrier.try_wait.parity.acquire.cta.shared::cta.b64 P, [%0], %1, 0x989680;\n\t"
        "@P bra D%=;\n\t"
        "bra W%=;\n\t"
        "D%=:\n\t}"
        :: "r"(mbar), "r"(phase) : "memory");
}
__device__ __forceinline__ void bulk_g2s(uint32_t dst, const void* src, uint32_t bytes, uint32_t mbar) {
    asm volatile("cp.async.bulk.shared::cluster.global.mbarrier::complete_tx::bytes [%0], [%1], %2, [%3];"
                 :: "r"(dst), "l"(src), "r"(bytes), "r"(mbar) : "memory");
}
__device__ __forceinline__ void bulk_s2g(void* dst, uint32_t src, uint32_t bytes) {
    asm volatile("cp.async.bulk.global.shared::cta.bulk_group [%0], [%1], %2;"
                 :: "l"(dst), "r"(src), "r"(bytes) : "memory");
}

// Warp-aggregated histogram add (fallback only).
__device__ __forceinline__ void hist_add(uint32_t* hist, uint32_t bin, bool pred, int lane) {
    unsigned act = __ballot_sync(0xffffffffu, pred);
    if (pred) {
        unsigned same   = __match_any_sync(act, bin);
        int      leader = __ffs(same) - 1;
        if (lane == leader) atomicAdd(&hist[bin], (uint32_t)__popc(same));
    }
}

extern __shared__ char smem[];

__global__ __launch_bounds__(NTHREADS)
void topk_mask_kernel(const float* __restrict__ A, float* __restrict__ out)
{
    const int tid  = threadIdx.x;
    const int lane = tid & 31;
    const int warp = tid >> 5;
    const size_t row = blockIdx.x;

    float4*   zbuf = reinterpret_cast<float4*>(smem + OFF_ZBUF);
    uint64_t* cand = reinterpret_cast<uint64_t*>(smem + OFF_CAND);
    uint32_t* wsum = reinterpret_cast<uint32_t*>(smem + OFF_WSUM);
    uint32_t* ctr  = reinterpret_cast<uint32_t*>(smem + OFF_CTR);   // cnt,b,kp,deg
    const uint32_t mb  = smem_u32(smem + OFF_MBAR);
    const uint32_t zsa = smem_u32(smem + OFF_ZBUF);
    const uint32_t bfa = smem_u32(smem + OFF_BUF);

    if (tid < 128) zbuf[tid] = make_float4(0.0f, 0.0f, 0.0f, 0.0f);  // 2KB zero tile
    if (tid == 0) { mbar_init(mb, 1); ctr[0] = 0; }
    __syncthreads();

    const float* arowf = A + row * (size_t)NN;
    float*       orowf = out + row * (size_t)NN;

    // Kick off the whole row's traffic: async read of A-row into smem + async
    // zero-fill of the output row. Warps sleep on the mbarrier while TMA streams.
    if (tid == 0) {
        asm volatile("fence.proxy.async.shared::cta;" ::: "memory");
        mbar_expect_tx(mb, ROWB);
        bulk_g2s(bfa,         arowf,        16384, mb);
        bulk_g2s(bfa + 16384, arowf + 4096, 16384, mb);
        #pragma unroll
        for (int k = 0; k < 16; ++k) bulk_s2g(orowf + k * 512, zsa, 2048);
        asm volatile("cp.async.bulk.commit_group;" ::: "memory");
    }
    mbar_wait(mb, 0);

    // ---- Sweep: branch-free mask accumulation (int compare on float bits) ----
    const uint4* bp = reinterpret_cast<const uint4*>(smem + OFF_BUF);
    uint32_t m = 0;
    #pragma unroll
    for (int u = 0; u < 8; ++u) {
        const uint4 v = bp[tid + u * NTHREADS];
        if ((int)v.x >= TBI) m |= 1u << (4 * u + 0);
        if ((int)v.y >= TBI) m |= 1u << (4 * u + 1);
        if ((int)v.z >= TBI) m |= 1u << (4 * u + 2);
        if ((int)v.w >= TBI) m |= 1u << (4 * u + 3);
    }

    // ---- Push: one shared-atomic reservation per active thread, tiny loop ----
    // Order in cand[] is timing-dependent, but the final output is not: exact
    // ranking over unique (value,index) keys is order-independent.
    {
        const int cnt = __popc(m);
        uint32_t off = 0;
        if (cnt) off = atomicAdd(&ctr[0], (uint32_t)cnt);
        const uint32_t* bw = reinterpret_cast<const uint32_t*>(smem + OFF_BUF);
        while (m) {
            const int b = __ffs(m) - 1; m &= m - 1;
            const uint32_t ei = (uint32_t)(((tid + ((b >> 2) << 8)) << 2) + (b & 3));
            if (off < FCAP) cand[off] = make_key(bw[ei], ei);
            ++off;
        }
    }
    __syncthreads();

    const uint32_t C = ctr[0];
    if (C >= KSEL && C <= FCAP) {
        if (tid == 0) asm volatile("cp.async.bulk.wait_group 0;" ::: "memory");
        __syncthreads();   // zeros committed before scatter

        // ---- Exact rank (value desc, index asc); scatter the KSEL winners ----
        for (uint32_t j = tid; j < C; j += NTHREADS) {
            const uint64_t kj = cand[j];
            uint32_t rr = 0;
            for (uint32_t m2 = 0; m2 < C; ++m2)
                rr += (cand[m2] > kj) ? 1u : 0u;          // broadcast LDS
            if (rr < KSEL) {
                const uint32_t idx = 0xFFFFu ^ (uint32_t)(kj & 0xFFFFu);
                orowf[idx] = __uint_as_float((uint32_t)(kj >> 16));
            }
        }
        return;
    }

    // ============== Exact fallback (rare), data from smem row buffer ==============
    uint32_t* hist = reinterpret_cast<uint32_t*>(smem + OFF_CAND);  // cand dead here
    if (tid == 0) asm volatile("cp.async.bulk.wait_group 0;" ::: "memory");
    if (tid < 4) ctr[tid] = 0;              // fb_count, sh_b, sh_kp, sh_deg
    hist[tid] = 0;
    __syncthreads();

    const float* bf = reinterpret_cast<const float*>(smem + OFF_BUF);
    for (int i = tid; i < NN; i += NTHREADS) {
        const float q = bf[i];
        const uint32_t bits = (q > 0.0f) ? __float_as_uint(q) : 0u;
        hist_add(hist, bits >> 24, bits != 0u, lane);
    }
    __syncthreads();

    {   // suffix scan over 256 byte bins
        const uint32_t v0 = hist[tid];
        uint32_t vv = v0;
        #pragma unroll
        for (int d = 1; d < 32; d <<= 1) {
            uint32_t o = __shfl_down_sync(0xffffffffu, vv, d);
            if (lane + d < 32) vv += o;
        }
        if (lane == 0) wsum[warp] = vv;
        __syncthreads();
        uint32_t hi = 0;
        #pragma unroll
        for (int w = 0; w < 8; ++w) if (w > warp) hi += wsum[w];
        const uint32_t s   = vv + hi;
        const uint32_t nxt = s - v0;
        if (tid == 0 && s < KSEL) ctr[3] = 1;
        if (s >= KSEL && nxt < KSEL) { ctr[1] = (uint32_t)tid; ctr[2] = KSEL - nxt; }
        __syncthreads();    // hist dead past this point
    }
    const uint32_t b   = ctr[1];
    const uint32_t kp  = ctr[2];
    const bool     deg = (ctr[3] != 0);
    uint64_t* fcand = reinterpret_cast<uint64_t*>(smem + OFF_CAND);  // overlays dead hist

    for (int i = tid; i < NN; i += NTHREADS) {
        const float q = bf[i];
        const uint32_t bits = (q > 0.0f) ? __float_as_uint(q) : 0u;
        if (deg) {
            if (bits) orowf[i] = q;                    // <K positives: keep all
        } else if (bits) {
            const uint32_t byte = bits >> 24;
            if (byte > b) orowf[i] = q;
            else if (byte == b) {
                const uint32_t pp = atomicAdd(&ctr[0], 1u);
                if (pp < FCAP) fcand[pp] = make_key(bits, (uint32_t)i);
            }
        }
    }
    __syncthreads();

    if (!deg) {
        const uint32_t C2 = ctr[0];
        if (C2 <= FCAP) {
            for (uint32_t j = tid; j < C2; j += NTHREADS) {
                const uint64_t kj = fcand[j];
                uint32_t rr = 0;
                for (uint32_t mm = 0; mm < C2; ++mm)
                    rr += (fcand[mm] > kj) ? 1u : 0u;
                if (rr < kp) {
                    const uint32_t idx = 0xFFFFu ^ (uint32_t)(kj & 0xFFFFu);
                    orowf[idx] = __uint_as_float((uint32_t)(kj >> 16));
                }
            }
        } else {
            // duplicate-heavy pathological rows: O(N) exact rank from smem
            for (int i = tid; i < NN; i += NTHREADS) {
                const float q = bf[i];
                const uint32_t bits = (q > 0.0f) ? __float_as_uint(q) : 0u;
                if (bits && (bits >> 24) == b) {
                    const uint64_t kj = make_key(bits, (uint32_t)i);
                    uint32_t rr = 0;
                    for (int j2 = 0; j2 < NN; ++j2) {
                        const float w2 = bf[j2];
                        const uint32_t wb = (w2 > 0.0f) ? __float_as_uint(w2) : 0u;
                        if (wb && (wb >> 24) == b && make_key(wb, (uint32_t)j2) > kj) ++rr;
                    }
                    if (rr < kp) orowf[i] = q;
                }
            }
        }
    }
}

extern "C" void kernel_launch(void* const* d_in, const int* in_sizes, int n_in,
                              void* d_out, int out_size) {
    const float* A   = (const float*)d_in[0];
    float*       out = (float*)d_out;
    (void)in_sizes; (void)n_in; (void)out_size;   // idx (d_in[1]) unused by the reference
    cudaFuncSetAttribute(topk_mask_kernel, cudaFuncAttributeMaxDynamicSharedMemorySize, SMEM_TOTAL);
    topk_mask_kernel<<<NN, NTHREADS, SMEM_TOTAL>>>(A, out);
}

// round 15
// speedup vs baseline: 1.3470x; 1.0042x over previous
#include <cuda_runtime.h>
#include <cstdint>

#define NN        8192
#define KSEL      64
#define NTHREADS  256
#define FCAP      320            // dense candidate cap (~16 sigma above E[C]=100)
#define THRESH    2.25f
#define TBI       0x40100000     // float bits of 2.25f (int compare valid: thresh > 0)

#define ROWB      (NN * 4)       // 32768-byte row buffer
#define HALFB     16384
#define OFF_BUF   0
#define OFF_ZBUF  32768          // 2048 zero tile
#define OFF_CAND  34816          // 2560 (320 x u64); fallback: hist(1KB) then fcand
#define OFF_WSUM  37376          // 32
#define OFF_CTR   37408          // 16: cand/fb count, sh_b, sh_kp, sh_deg
#define OFF_MBAR  37424          // 16: two mbarriers
#define SMEM_TOTAL 37440

__device__ __forceinline__ uint64_t make_key(uint32_t bits, uint32_t idx) {
    // larger key == larger value; ties -> smaller index (top_k order)
    return ((uint64_t)bits << 16) | (uint64_t)(0xFFFFu ^ idx);
}
__device__ __forceinline__ uint32_t smem_u32(const void* p) {
    return (uint32_t)__cvta_generic_to_shared(p);
}
__device__ __forceinline__ void mbar_init(uint32_t mbar, uint32_t cnt) {
    asm volatile("mbarrier.init.shared.b64 [%0], %1;" :: "r"(mbar), "r"(cnt) : "memory");
}
__device__ __forceinline__ void mbar_expect_tx(uint32_t mbar, uint32_t bytes) {
    asm volatile("mbarrier.arrive.expect_tx.shared.b64 _, [%0], %1;" :: "r"(mbar), "r"(bytes) : "memory");
}
__device__ __forceinline__ void mbar_wait(uint32_t mbar, uint32_t phase) {
    asm volatile(
        "{\n\t.reg .pred P;\n\t"
        "W%=:\n\t"
        "mbarrier.try_wait.parity.acquire.cta.shared::cta.b64 P, [%0], %1, 0x989680;\n\t"
        "@P bra D%=;\n\t"
        "bra W%=;\n\t"
        "D%=:\n\t}"
        :: "r"(mbar), "r"(phase) : "memory");
}
__device__ __forceinline__ void bulk_g2s(uint32_t dst, const void* src, uint32_t bytes, uint32_t mbar) {
    asm volatile("cp.async.bulk.shared::cluster.global.mbarrier::complete_tx::bytes [%0], [%1], %2, [%3];"
                 :: "r"(dst), "l"(src), "r"(bytes), "r"(mbar) : "memory");
}
__device__ __forceinline__ void bulk_s2g(void* dst, uint32_t src, uint32_t bytes) {
    asm volatile("cp.async.bulk.global.shared::cta.bulk_group [%0], [%1], %2;"
                 :: "l"(dst), "r"(src), "r"(bytes) : "memory");
}

// Warp-aggregated histogram add (fallback only).
__device__ __forceinline__ void hist_add(uint32_t* hist, uint32_t bin, bool pred, int lane) {
    unsigned act = __ballot_sync(0xffffffffu, pred);
    if (pred) {
        unsigned same   = __match_any_sync(act, bin);
        int      leader = __ffs(same) - 1;
        if (lane == leader) atomicAdd(&hist[bin], (uint32_t)__popc(same));
    }
}

extern __shared__ char smem[];

__global__ __launch_bounds__(NTHREADS)
void topk_mask_kernel(const float* __restrict__ A, float* __restrict__ out)
{
    const int tid  = threadIdx.x;
    const int lane = tid & 31;
    const int warp = tid >> 5;
    const size_t row = blockIdx.x;

    float4*   zbuf = reinterpret_cast<float4*>(smem + OFF_ZBUF);
    uint64_t* cand = reinterpret_cast<uint64_t*>(smem + OFF_CAND);
    uint32_t* wsum = reinterpret_cast<uint32_t*>(smem + OFF_WSUM);
    uint32_t* ctr  = reinterpret_cast<uint32_t*>(smem + OFF_CTR);   // cnt,b,kp,deg
    const uint32_t mb0 = smem_u32(smem + OFF_MBAR);
    const uint32_t mb1 = smem_u32(smem + OFF_MBAR + 8);
    const uint32_t zsa = smem_u32(smem + OFF_ZBUF);
    const uint32_t bfa = smem_u32(smem + OFF_BUF);

    if (tid < 128) zbuf[tid] = make_float4(0.0f, 0.0f, 0.0f, 0.0f);  // 2KB zero tile
    if (tid == 0) { mbar_init(mb0, 1); mbar_init(mb1, 1); ctr[0] = 0; }
    __syncthreads();

    const float* arowf = A + row * (size_t)NN;
    float*       orowf = out + row * (size_t)NN;

    // Kick off the whole row's traffic: two 16KB async reads (separate
    // mbarriers so the sweep can start on half 0 while half 1 streams) and the
    // async zero-fill group for the output row.
    if (tid == 0) {
        asm volatile("fence.proxy.async.shared::cta;" ::: "memory");
        mbar_expect_tx(mb0, HALFB);
        bulk_g2s(bfa,         arowf,        HALFB, mb0);
        mbar_expect_tx(mb1, HALFB);
        bulk_g2s(bfa + HALFB, arowf + 4096, HALFB, mb1);
        #pragma unroll
        for (int k = 0; k < 16; ++k) bulk_s2g(orowf + k * 512, zsa, 2048);
        asm volatile("cp.async.bulk.commit_group;" ::: "memory");
    }

    // ---- Sweep: branch-free mask accumulation (int compare on float bits) ----
    const uint4* bp = reinterpret_cast<const uint4*>(smem + OFF_BUF);
    uint32_t m = 0;
    mbar_wait(mb0, 0);                       // half 0 resident
    #pragma unroll
    for (int u = 0; u < 4; ++u) {
        const uint4 v = bp[tid + u * NTHREADS];
        if ((int)v.x >= TBI) m |= 1u << (4 * u + 0);
        if ((int)v.y >= TBI) m |= 1u << (4 * u + 1);
        if ((int)v.z >= TBI) m |= 1u << (4 * u + 2);
        if ((int)v.w >= TBI) m |= 1u << (4 * u + 3);
    }
    mbar_wait(mb1, 0);                       // half 1 resident (usually already done)
    #pragma unroll
    for (int u = 4; u < 8; ++u) {
        const uint4 v = bp[tid + u * NTHREADS];
        if ((int)v.x >= TBI) m |= 1u << (4 * u + 0);
        if ((int)v.y >= TBI) m |= 1u << (4 * u + 1);
        if ((int)v.z >= TBI) m |= 1u << (4 * u + 2);
        if ((int)v.w >= TBI) m |= 1u << (4 * u + 3);
    }

    // ---- Push: one shared-atomic reservation per active thread, tiny loop ----
    // Order in cand[] is timing-dependent, but the final output is not: exact
    // ranking over unique (value,index) keys is order-independent.
    {
        const int cnt = __popc(m);
        uint32_t off = 0;
        if (cnt) off = atomicAdd(&ctr[0], (uint32_t)cnt);
        const uint32_t* bw = reinterpret_cast<const uint32_t*>(smem + OFF_BUF);
        while (m) {
            const int b = __ffs(m) - 1; m &= m - 1;
            const uint32_t ei = (uint32_t)(((tid + ((b >> 2) << 8)) << 2) + (b & 3));
            if (off < FCAP) cand[off] = make_key(bw[ei], ei);
            ++off;
        }
    }
    __syncthreads();

    const uint32_t C = ctr[0];
    if (C >= KSEL && C <= FCAP) {
        if (tid == 0) asm volatile("cp.async.bulk.wait_group 0;" ::: "memory");
        __syncthreads();   // zeros committed before scatter

        // ---- Exact rank (value desc, index asc); scatter the KSEL winners ----
        for (uint32_t j = tid; j < C; j += NTHREADS) {
            const uint64_t kj = cand[j];
            uint32_t rr = 0;
            for (uint32_t m2 = 0; m2 < C; ++m2)
                rr += (cand[m2] > kj) ? 1u : 0u;          // broadcast LDS
            if (rr < KSEL) {
                const uint32_t idx = 0xFFFFu ^ (uint32_t)(kj & 0xFFFFu);
                orowf[idx] = __uint_as_float((uint32_t)(kj >> 16));
            }
        }
        return;
    }

    // ============== Exact fallback (rare), data from smem row buffer ==============
    uint32_t* hist = reinterpret_cast<uint32_t*>(smem + OFF_CAND);  // cand dead here
    if (tid == 0) asm volatile("cp.async.bulk.wait_group 0;" ::: "memory");
    if (tid < 4) ctr[tid] = 0;              // fb_count, sh_b, sh_kp, sh_deg
    hist[tid] = 0;
    __syncthreads();

    const float* bf = reinterpret_cast<const float*>(smem + OFF_BUF);
    for (int i = tid; i < NN; i += NTHREADS) {
        const float q = bf[i];
        const uint32_t bits = (q > 0.0f) ? __float_as_uint(q) : 0u;
        hist_add(hist, bits >> 24, bits != 0u, lane);
    }
    __syncthreads();

    {   // suffix scan over 256 byte bins
        const uint32_t v0 = hist[tid];
        uint32_t vv = v0;
        #pragma unroll
        for (int d = 1; d < 32; d <<= 1) {
            uint32_t o = __shfl_down_sync(0xffffffffu, vv, d);
            if (lane + d < 32) vv += o;
        }
        if (lane == 0) wsum[warp] = vv;
        __syncthreads();
        uint32_t hi = 0;
        #pragma unroll
        for (int w = 0; w < 8; ++w) if (w > warp) hi += wsum[w];
        const uint32_t s   = vv + hi;
        const uint32_t nxt = s - v0;
        if (tid == 0 && s < KSEL) ctr[3] = 1;
        if (s >= KSEL && nxt < KSEL) { ctr[1] = (uint32_t)tid; ctr[2] = KSEL - nxt; }
        __syncthreads();    // hist dead past this point
    }
    const uint32_t b   = ctr[1];
    const uint32_t kp  = ctr[2];
    const bool     deg = (ctr[3] != 0);
    uint64_t* fcand = reinterpret_cast<uint64_t*>(smem + OFF_CAND);  // overlays dead hist

    for (int i = tid; i < NN; i += NTHREADS) {
        const float q = bf[i];
        const uint32_t bits = (q > 0.0f) ? __float_as_uint(q) : 0u;
        if (deg) {
            if (bits) orowf[i] = q;                    // <K positives: keep all
        } else if (bits) {
            const uint32_t byte = bits >> 24;
            if (byte > b) orowf[i] = q;
            else if (byte == b) {
                const uint32_t pp = atomicAdd(&ctr[0], 1u);
                if (pp < FCAP) fcand[pp] = make_key(bits, (uint32_t)i);
            }
        }
    }
    __syncthreads();

    if (!deg) {
        const uint32_t C2 = ctr[0];
        if (C2 <= FCAP) {
            for (uint32_t j = tid; j < C2; j += NTHREADS) {
                const uint64_t kj = fcand[j];
                uint32_t rr = 0;
                for (uint32_t mm = 0; mm < C2; ++mm)
                    rr += (fcand[mm] > kj) ? 1u : 0u;
                if (rr < kp) {
                    const uint32_t idx = 0xFFFFu ^ (uint32_t)(kj & 0xFFFFu);
                    orowf[idx] = __uint_as_float((uint32_t)(kj >> 16));
                }
            }
        } else {
            // duplicate-heavy pathological rows: O(N) exact rank from smem
            for (int i = tid; i < NN; i += NTHREADS) {
                const float q = bf[i];
                const uint32_t bits = (q > 0.0f) ? __float_as_uint(q) : 0u;
                if (bits && (bits >> 24) == b) {
                    const uint64_t kj = make_key(bits, (uint32_t)i);
                    uint32_t rr = 0;
                    for (int j2 = 0; j2 < NN; ++j2) {
                        const float w2 = bf[j2];
                        const uint32_t wb = (w2 > 0.0f) ? __float_as_uint(w2) : 0u;
                        if (wb && (wb >> 24) == b && make_key(wb, (uint32_t)j2) > kj) ++rr;
                    }
                    if (rr < kp) orowf[i] = q;
                }
            }
        }
    }
}

extern "C" void kernel_launch(void* const* d_in, const int* in_sizes, int n_in,
                              void* d_out, int out_size) {
    const float* A   = (const float*)d_in[0];
    float*       out = (float*)d_out;
    (void)in_sizes; (void)n_in; (void)out_size;   // idx (d_in[1]) unused by the reference
    cudaFuncSetAttribute(topk_mask_kernel, cudaFuncAttributeMaxDynamicSharedMemorySize, SMEM_TOTAL);
    topk_mask_kernel<<<NN, NTHREADS, SMEM_TOTAL>>>(A, out);
}